// round 1
// baseline (speedup 1.0000x reference)
#include <cuda_runtime.h>
#include <math.h>

#define NMAX 4096
#define DDIM 128
#define POS_W 2.0f
#define NEG_W 40.0f
#define MARGIN 0.1f
#define THRESH 0.5f

// ---------------- scratch (no allocations allowed) ----------------
__device__ float    g_xn[NMAX * DDIM];                 // normalized rows
__device__ int      g_lab[NMAX];                       // labels as int32
__device__ float    g_S[(size_t)NMAX * NMAX];          // 64MB similarity matrix
__device__ unsigned g_minpos[NMAX];                    // encoded-float atomic min
__device__ unsigned g_maxneg[NMAX];                    // encoded-float atomic max
__device__ float    g_part[3 * (NMAX / 8)];            // per-block partials
__device__ int      g_lflag;                           // 1 => labels are int32

// ordered-float encoding for unsigned atomicMin/Max
__device__ __forceinline__ unsigned fenc(float f) {
    unsigned u = __float_as_uint(f);
    return (u & 0x80000000u) ? ~u : (u | 0x80000000u);
}
__device__ __forceinline__ float fdec(unsigned e) {
    unsigned u = (e & 0x80000000u) ? (e ^ 0x80000000u) : ~e;
    return __uint_as_float(u);
}

// ---------------- k_detect: int32 vs int64 label buffer ----------------
// int64 labels (0..63) viewed as int32 have all odd words == 0.
__global__ void k_detect(const int* __restrict__ lab32, int N) {
    __shared__ int s;
    if (threadIdx.x == 0) s = 0;
    __syncthreads();
    int any = 0;
    for (int i = 1 + 2 * (int)threadIdx.x; i < N; i += 2 * (int)blockDim.x)
        if (lab32[i] != 0) any = 1;
    if (any) atomicOr(&s, 1);
    __syncthreads();
    if (threadIdx.x == 0) g_lflag = s;
}

// ---------------- k_prep: convert labels, init min/max ----------------
__global__ void k_prep(const void* __restrict__ labv, int N) {
    int i = blockIdx.x * blockDim.x + threadIdx.x;
    if (i >= N) return;
    int v;
    if (g_lflag) v = ((const int*)labv)[i];
    else         v = (int)(((const long long*)labv)[i]);
    g_lab[i]    = v;
    g_minpos[i] = fenc(1e9f);
    g_maxneg[i] = fenc(-1e9f);
}

// ---------------- k_norm: L2 row normalize (warp per row) ----------------
__global__ void k_norm(const float* __restrict__ x, int N) {
    int warp = threadIdx.x >> 5, lane = threadIdx.x & 31;
    int row = blockIdx.x * 8 + warp;
    if (row >= N) return;
    float4 v = *(const float4*)(x + (size_t)row * DDIM + lane * 4);
    float ss = v.x * v.x + v.y * v.y + v.z * v.z + v.w * v.w;
#pragma unroll
    for (int o = 16; o > 0; o >>= 1) ss += __shfl_xor_sync(0xffffffffu, ss, o);
    float inv = 1.0f / sqrtf(ss);
    float4 o4 = make_float4(v.x * inv, v.y * inv, v.z * inv, v.w * inv);
    *(float4*)(g_xn + (size_t)row * DDIM + lane * 4) = o4;
}

// ---------------- k_gemm: S tile + fused masked min/max epilogue ----------------
// 128x128 tile per block, 256 threads, 8x8 micro-tile (4+4 split rows/cols).
#define SPAD 132
__global__ __launch_bounds__(256, 1) void k_gemm(int N) {
    extern __shared__ float smem[];
    float* As = smem;                 // [128][SPAD], transposed: As[k][m]
    float* Bs = smem + 128 * SPAD;    // [128][SPAD]

    int tid = threadIdx.x;
    int row0 = blockIdx.y * 128, col0 = blockIdx.x * 128;

    // load both tiles transposed into smem (conflict-free writes: m varies with tid)
#pragma unroll
    for (int t = 0; t < 16; t++) {
        int idx = t * 256 + tid;
        int m = idx & 127, k4 = idx >> 7;
        float4 a = *(const float4*)(g_xn + (size_t)(row0 + m) * DDIM + k4 * 4);
        As[(k4 * 4 + 0) * SPAD + m] = a.x;
        As[(k4 * 4 + 1) * SPAD + m] = a.y;
        As[(k4 * 4 + 2) * SPAD + m] = a.z;
        As[(k4 * 4 + 3) * SPAD + m] = a.w;
        float4 b = *(const float4*)(g_xn + (size_t)(col0 + m) * DDIM + k4 * 4);
        Bs[(k4 * 4 + 0) * SPAD + m] = b.x;
        Bs[(k4 * 4 + 1) * SPAD + m] = b.y;
        Bs[(k4 * 4 + 2) * SPAD + m] = b.z;
        Bs[(k4 * 4 + 3) * SPAD + m] = b.w;
    }
    __syncthreads();

    int tx = tid & 15, ty = tid >> 4;
    float acc[8][8];
#pragma unroll
    for (int i = 0; i < 8; i++)
#pragma unroll
        for (int j = 0; j < 8; j++) acc[i][j] = 0.f;

#pragma unroll 8
    for (int k = 0; k < 128; k++) {
        float a[8], b[8];
        *(float4*)(a)     = *(const float4*)&As[k * SPAD + ty * 4];
        *(float4*)(a + 4) = *(const float4*)&As[k * SPAD + 64 + ty * 4];
        *(float4*)(b)     = *(const float4*)&Bs[k * SPAD + tx * 4];
        *(float4*)(b + 4) = *(const float4*)&Bs[k * SPAD + 64 + tx * 4];
#pragma unroll
        for (int i = 0; i < 8; i++)
#pragma unroll
            for (int j = 0; j < 8; j++) acc[i][j] += a[i] * b[j];
    }

    // epilogue: masked hardest-pos min / hardest-neg max, plus coalesced S store
    int li[8], lj[8], rr[8], cc[8];
#pragma unroll
    for (int i = 0; i < 8; i++) {
        int rl = (i < 4) ? (ty * 4 + i) : (64 + ty * 4 + i - 4);
        int cl = (i < 4) ? (tx * 4 + i) : (64 + tx * 4 + i - 4);
        rr[i] = row0 + rl; cc[i] = col0 + cl;
        li[i] = g_lab[rr[i]]; lj[i] = g_lab[cc[i]];
    }
#pragma unroll
    for (int i = 0; i < 8; i++) {
        float mn = 1e9f, mx = -1e9f;
#pragma unroll
        for (int j = 0; j < 8; j++) {
            float s = acc[i][j];
            if (li[i] == lj[j]) { if (rr[i] != cc[j] && s < mn) mn = s; }
            else                { if (s > mx) mx = s; }
        }
        size_t base = (size_t)rr[i] * N;
        *(float4*)(g_S + base + col0 + tx * 4) =
            make_float4(acc[i][0], acc[i][1], acc[i][2], acc[i][3]);
        *(float4*)(g_S + base + col0 + 64 + tx * 4) =
            make_float4(acc[i][4], acc[i][5], acc[i][6], acc[i][7]);
#pragma unroll
        for (int o = 8; o > 0; o >>= 1) {
            mn = fminf(mn, __shfl_xor_sync(0xffffffffu, mn, o));
            mx = fmaxf(mx, __shfl_xor_sync(0xffffffffu, mx, o));
        }
        if (tx == 0) {
            atomicMin(&g_minpos[rr[i]], fenc(mn));
            atomicMax(&g_maxneg[rr[i]], fenc(mx));
        }
    }
}

// ---------------- k_sums: mining + masked exp sums (warp per row) ----------------
__global__ __launch_bounds__(256) void k_sums(int N) {
    __shared__ int slbl[NMAX];
    __shared__ float spt[8], snt[8], sct[8];
    for (int j = threadIdx.x; j < N; j += 256) slbl[j] = g_lab[j];
    __syncthreads();

    int warp = threadIdx.x >> 5, lane = threadIdx.x & 31;
    int i = blockIdx.x * 8 + warp;

    float minp = fdec(g_minpos[i]);
    float maxn = fdec(g_maxneg[i]);
    int li = slbl[i];
    float psum = 0.f, nsum = 0.f;
    int psel = 0, nsel = 0;
    const float* Srow = g_S + (size_t)i * N;

    for (int j0 = lane * 4; j0 < N; j0 += 128) {
        float4 s4 = *(const float4*)(Srow + j0);
        float sv[4] = {s4.x, s4.y, s4.z, s4.w};
#pragma unroll
        for (int q = 0; q < 4; q++) {
            int j = j0 + q;
            float s = sv[q];
            if (slbl[j] == li) {
                if (j != i && (s - MARGIN < maxn)) {
                    psel = 1; psum += __expf(-POS_W * (s - THRESH));
                }
            } else {
                if (s + MARGIN > minp) {
                    nsel = 1; nsum += __expf(NEG_W * (s - THRESH));
                }
            }
        }
    }
#pragma unroll
    for (int o = 16; o > 0; o >>= 1) {
        psum += __shfl_xor_sync(0xffffffffu, psum, o);
        nsum += __shfl_xor_sync(0xffffffffu, nsum, o);
    }
    psel = (__ballot_sync(0xffffffffu, psel) != 0);
    nsel = (__ballot_sync(0xffffffffu, nsel) != 0);

    if (lane == 0) {
        bool pos_any = (minp < 5e8f);
        bool neg_any = (maxn > -5e8f);
        bool valid = pos_any && neg_any && psel && nsel;
        spt[warp] = valid ? (log1pf(psum) * (1.0f / POS_W)) : 0.f;
        snt[warp] = valid ? (log1pf(nsum) * (1.0f / NEG_W)) : 0.f;
        sct[warp] = valid ? 1.f : 0.f;
    }
    __syncthreads();
    if (threadIdx.x == 0) {
        float pt = 0.f, nt = 0.f, ct = 0.f;
        for (int w = 0; w < 8; w++) { pt += spt[w]; nt += snt[w]; ct += sct[w]; }
        g_part[blockIdx.x * 3 + 0] = pt;
        g_part[blockIdx.x * 3 + 1] = nt;
        g_part[blockIdx.x * 3 + 2] = ct;
    }
}

// ---------------- k_final: deterministic reduction + output ----------------
__global__ void k_final(float* out, int out_size, int nb) {
    __shared__ float sp[256], sn[256], sc[256];
    int t = threadIdx.x;
    float pt = 0.f, nt = 0.f, ct = 0.f;
    for (int b = t; b < nb; b += 256) {
        pt += g_part[b * 3 + 0];
        nt += g_part[b * 3 + 1];
        ct += g_part[b * 3 + 2];
    }
    sp[t] = pt; sn[t] = nt; sc[t] = ct;
    __syncthreads();
    for (int o = 128; o > 0; o >>= 1) {
        if (t < o) { sp[t] += sp[t + o]; sn[t] += sn[t + o]; sc[t] += sc[t + o]; }
        __syncthreads();
    }
    if (t == 0) {
        float cnt = fmaxf(sc[0], 1.f);
        float pm = sp[0] / cnt, nm = sn[0] / cnt;
        out[0] = pm + nm;
        if (out_size > 1) out[1] = pm;
        if (out_size > 2) out[2] = nm;
        for (int z = 3; z < out_size; z++) out[z] = 0.f;
    }
}

// ---------------- launch ----------------
extern "C" void kernel_launch(void* const* d_in, const int* in_sizes, int n_in,
                              void* d_out, int out_size) {
    const float* batch = (const float*)d_in[0];
    const void*  lab   = d_in[1];
    int N = in_sizes[1];
    if (N > NMAX) N = NMAX;

    static bool attr_done = false;
    if (!attr_done) {
        cudaFuncSetAttribute(k_gemm, cudaFuncAttributeMaxDynamicSharedMemorySize,
                             2 * 128 * SPAD * (int)sizeof(float));
        attr_done = true;
    }

    k_detect<<<1, 256>>>((const int*)lab, N);
    k_prep<<<(N + 255) / 256, 256>>>(lab, N);
    k_norm<<<(N + 7) / 8, 256>>>(batch, N);
    dim3 gg(N / 128, N / 128);
    k_gemm<<<gg, 256, 2 * 128 * SPAD * (int)sizeof(float)>>>(N);
    k_sums<<<(N + 7) / 8, 256>>>(N);
    k_final<<<1, 256>>>((float*)d_out, out_size, (N + 7) / 8);
}

// round 2
// speedup vs baseline: 1.2406x; 1.2406x over previous
#include <cuda_runtime.h>
#include <math.h>

#define NMAX 4096
#define DDIM 128
#define POS_W 2.0f
#define NEG_W 40.0f
#define MARGIN 0.1f
#define THRESH 0.5f

// ---------------- scratch (no allocations allowed) ----------------
__device__ float    g_xn[NMAX * DDIM];                 // normalized rows
__device__ int      g_lab[NMAX];                       // labels as int32
__device__ float    g_S[(size_t)NMAX * NMAX];          // 64MB similarity matrix
__device__ unsigned g_minpos[NMAX];                    // encoded-float atomic min
__device__ unsigned g_maxneg[NMAX];                    // encoded-float atomic max
__device__ float    g_part[3 * (NMAX / 8)];            // per-block partials
__device__ int      g_lflag;                           // 1 => labels are int32

// ordered-float encoding for unsigned atomicMin/Max
__device__ __forceinline__ unsigned fenc(float f) {
    unsigned u = __float_as_uint(f);
    return (u & 0x80000000u) ? ~u : (u | 0x80000000u);
}
__device__ __forceinline__ float fdec(unsigned e) {
    unsigned u = (e & 0x80000000u) ? (e ^ 0x80000000u) : ~e;
    return __uint_as_float(u);
}

// ---------------- k_detect: int32 vs int64 label buffer ----------------
__global__ void k_detect(const int* __restrict__ lab32, int N) {
    __shared__ int s;
    if (threadIdx.x == 0) s = 0;
    __syncthreads();
    int any = 0;
    for (int i = 1 + 2 * (int)threadIdx.x; i < N; i += 2 * (int)blockDim.x)
        if (lab32[i] != 0) any = 1;
    if (any) atomicOr(&s, 1);
    __syncthreads();
    if (threadIdx.x == 0) g_lflag = s;
}

// ---------------- k_prep: convert labels, init min/max ----------------
__global__ void k_prep(const void* __restrict__ labv, int N) {
    int i = blockIdx.x * blockDim.x + threadIdx.x;
    if (i >= N) return;
    int v;
    if (g_lflag) v = ((const int*)labv)[i];
    else         v = (int)(((const long long*)labv)[i]);
    g_lab[i]    = v;
    g_minpos[i] = fenc(1e9f);
    g_maxneg[i] = fenc(-1e9f);
}

// ---------------- k_norm: L2 row normalize (warp per row) ----------------
__global__ void k_norm(const float* __restrict__ x, int N) {
    int warp = threadIdx.x >> 5, lane = threadIdx.x & 31;
    int row = blockIdx.x * 8 + warp;
    if (row >= N) return;
    float4 v = *(const float4*)(x + (size_t)row * DDIM + lane * 4);
    float ss = v.x * v.x + v.y * v.y + v.z * v.z + v.w * v.w;
#pragma unroll
    for (int o = 16; o > 0; o >>= 1) ss += __shfl_xor_sync(0xffffffffu, ss, o);
    float inv = 1.0f / sqrtf(ss);
    float4 o4 = make_float4(v.x * inv, v.y * inv, v.z * inv, v.w * inv);
    *(float4*)(g_xn + (size_t)row * DDIM + lane * 4) = o4;
}

// ---------------- k_gemm: symmetric-aware S tiles + fused min/max ----------------
// Only upper-triangular block-tiles (by <= bx). Off-diagonal tiles also write
// the transposed tile and contribute column-wise stats.
#define SPAD 132
__global__ __launch_bounds__(256, 1) void k_gemm(int N) {
    extern __shared__ float smem[];
    float* As = smem;                 // [128][SPAD], transposed: As[k][m]
    float* Bs = smem + 128 * SPAD;

    int tid = threadIdx.x;

    // map linear block id -> upper-triangular (bx, by) with by <= bx
    int t = blockIdx.x;
    int bx = (int)((sqrtf(8.0f * (float)t + 1.0f) - 1.0f) * 0.5f);
    while ((bx + 1) * (bx + 2) / 2 <= t) bx++;
    while (bx * (bx + 1) / 2 > t) bx--;
    int by = t - bx * (bx + 1) / 2;

    int row0 = by * 128, col0 = bx * 128;
    bool diag = (bx == by);

#pragma unroll
    for (int tt = 0; tt < 16; tt++) {
        int idx = tt * 256 + tid;
        int m = idx & 127, k4 = idx >> 7;
        float4 a = *(const float4*)(g_xn + (size_t)(row0 + m) * DDIM + k4 * 4);
        As[(k4 * 4 + 0) * SPAD + m] = a.x;
        As[(k4 * 4 + 1) * SPAD + m] = a.y;
        As[(k4 * 4 + 2) * SPAD + m] = a.z;
        As[(k4 * 4 + 3) * SPAD + m] = a.w;
        float4 b = *(const float4*)(g_xn + (size_t)(col0 + m) * DDIM + k4 * 4);
        Bs[(k4 * 4 + 0) * SPAD + m] = b.x;
        Bs[(k4 * 4 + 1) * SPAD + m] = b.y;
        Bs[(k4 * 4 + 2) * SPAD + m] = b.z;
        Bs[(k4 * 4 + 3) * SPAD + m] = b.w;
    }
    __syncthreads();

    int tx = tid & 15, ty = tid >> 4;
    float acc[8][8];
#pragma unroll
    for (int i = 0; i < 8; i++)
#pragma unroll
        for (int j = 0; j < 8; j++) acc[i][j] = 0.f;

#pragma unroll 8
    for (int k = 0; k < 128; k++) {
        float a[8], b[8];
        *(float4*)(a)     = *(const float4*)&As[k * SPAD + ty * 4];
        *(float4*)(a + 4) = *(const float4*)&As[k * SPAD + 64 + ty * 4];
        *(float4*)(b)     = *(const float4*)&Bs[k * SPAD + tx * 4];
        *(float4*)(b + 4) = *(const float4*)&Bs[k * SPAD + 64 + tx * 4];
#pragma unroll
        for (int i = 0; i < 8; i++)
#pragma unroll
            for (int j = 0; j < 8; j++) acc[i][j] += a[i] * b[j];
    }

    // ---- epilogue ----
    int li[8], lj[8], rr[8], cc[8];
#pragma unroll
    for (int i = 0; i < 8; i++) {
        int rl = (i < 4) ? (ty * 4 + i) : (64 + ty * 4 + i - 4);
        int cl = (i < 4) ? (tx * 4 + i) : (64 + tx * 4 + i - 4);
        rr[i] = row0 + rl; cc[i] = col0 + cl;
        li[i] = g_lab[rr[i]]; lj[i] = g_lab[cc[i]];
    }

    // per-thread column partials (for transposed contribution)
    float cmn[8], cmx[8];
#pragma unroll
    for (int j = 0; j < 8; j++) { cmn[j] = 1e9f; cmx[j] = -1e9f; }

#pragma unroll
    for (int i = 0; i < 8; i++) {
        float mn = 1e9f, mx = -1e9f;
#pragma unroll
        for (int j = 0; j < 8; j++) {
            float s = acc[i][j];
            bool same = (li[i] == lj[j]);
            bool nd   = (rr[i] != cc[j]);
            if (same) {
                if (nd && s < mn) mn = s;
                if (nd && s < cmn[j]) cmn[j] = s;
            } else {
                if (s > mx) mx = s;
                if (s > cmx[j]) cmx[j] = s;
            }
        }
        size_t base = (size_t)rr[i] * N;
        *(float4*)(g_S + base + col0 + tx * 4) =
            make_float4(acc[i][0], acc[i][1], acc[i][2], acc[i][3]);
        *(float4*)(g_S + base + col0 + 64 + tx * 4) =
            make_float4(acc[i][4], acc[i][5], acc[i][6], acc[i][7]);
#pragma unroll
        for (int o = 8; o > 0; o >>= 1) {
            mn = fminf(mn, __shfl_xor_sync(0xffffffffu, mn, o));
            mx = fmaxf(mx, __shfl_xor_sync(0xffffffffu, mx, o));
        }
        if (tx == 0) {
            atomicMin(&g_minpos[rr[i]], fenc(mn));
            atomicMax(&g_maxneg[rr[i]], fenc(mx));
        }
    }

    if (!diag) {
        // transposed tile store: for column j, acc[0..3][j] are contiguous rows
#pragma unroll
        for (int j = 0; j < 8; j++) {
            size_t baseT = (size_t)cc[j] * N;
            *(float4*)(g_S + baseT + row0 + ty * 4) =
                make_float4(acc[0][j], acc[1][j], acc[2][j], acc[3][j]);
            *(float4*)(g_S + baseT + row0 + 64 + ty * 4) =
                make_float4(acc[4][j], acc[5][j], acc[6][j], acc[7][j]);
        }

        // column stats -> stats for rows cc[j]
        // pair-reduce across ty (lane ^ 16 is same tx, ty+-1)
#pragma unroll
        for (int j = 0; j < 8; j++) {
            cmn[j] = fminf(cmn[j], __shfl_xor_sync(0xffffffffu, cmn[j], 16));
            cmx[j] = fmaxf(cmx[j], __shfl_xor_sync(0xffffffffu, cmx[j], 16));
        }
        __syncthreads();           // mainloop + epilogue smem reads done
        float* red_mn = smem;      // [8][128]
        float* red_mx = smem + 8 * 128;
        int warp = tid >> 5, lane = tid & 31;
        if (lane < 16) {
#pragma unroll
            for (int j = 0; j < 8; j++) {
                int cl = (j < 4) ? (tx * 4 + j) : (64 + tx * 4 + j - 4);
                red_mn[warp * 128 + cl] = cmn[j];
                red_mx[warp * 128 + cl] = cmx[j];
            }
        }
        __syncthreads();
        if (tid < 128) {
            float m = 1e9f, M = -1e9f;
#pragma unroll
            for (int w = 0; w < 8; w++) {
                m = fminf(m, red_mn[w * 128 + tid]);
                M = fmaxf(M, red_mx[w * 128 + tid]);
            }
            atomicMin(&g_minpos[col0 + tid], fenc(m));
            atomicMax(&g_maxneg[col0 + tid], fenc(M));
        }
    }
}

// ---------------- k_sums: mining + masked exp sums (warp per row) ----------------
__global__ __launch_bounds__(256) void k_sums(int N) {
    __shared__ int slbl[NMAX];
    __shared__ float spt[8], snt[8], sct[8];
    for (int j = threadIdx.x; j < N; j += 256) slbl[j] = g_lab[j];
    __syncthreads();

    int warp = threadIdx.x >> 5, lane = threadIdx.x & 31;
    int i = blockIdx.x * 8 + warp;

    float minp = fdec(g_minpos[i]);
    float maxn = fdec(g_maxneg[i]);
    int li = slbl[i];
    float psum = 0.f, nsum = 0.f;
    int psel = 0, nsel = 0;
    const float* Srow = g_S + (size_t)i * N;

    for (int j0 = lane * 4; j0 < N; j0 += 128) {
        float4 s4 = *(const float4*)(Srow + j0);
        float sv[4] = {s4.x, s4.y, s4.z, s4.w};
#pragma unroll
        for (int q = 0; q < 4; q++) {
            int j = j0 + q;
            float s = sv[q];
            if (slbl[j] == li) {
                if (j != i && (s - MARGIN < maxn)) {
                    psel = 1; psum += __expf(-POS_W * (s - THRESH));
                }
            } else {
                if (s + MARGIN > minp) {
                    nsel = 1; nsum += __expf(NEG_W * (s - THRESH));
                }
            }
        }
    }
#pragma unroll
    for (int o = 16; o > 0; o >>= 1) {
        psum += __shfl_xor_sync(0xffffffffu, psum, o);
        nsum += __shfl_xor_sync(0xffffffffu, nsum, o);
    }
    psel = (__ballot_sync(0xffffffffu, psel) != 0);
    nsel = (__ballot_sync(0xffffffffu, nsel) != 0);

    if (lane == 0) {
        bool pos_any = (minp < 5e8f);
        bool neg_any = (maxn > -5e8f);
        bool valid = pos_any && neg_any && psel && nsel;
        spt[warp] = valid ? (log1pf(psum) * (1.0f / POS_W)) : 0.f;
        snt[warp] = valid ? (log1pf(nsum) * (1.0f / NEG_W)) : 0.f;
        sct[warp] = valid ? 1.f : 0.f;
    }
    __syncthreads();
    if (threadIdx.x == 0) {
        float pt = 0.f, nt = 0.f, ct = 0.f;
        for (int w = 0; w < 8; w++) { pt += spt[w]; nt += snt[w]; ct += sct[w]; }
        g_part[blockIdx.x * 3 + 0] = pt;
        g_part[blockIdx.x * 3 + 1] = nt;
        g_part[blockIdx.x * 3 + 2] = ct;
    }
}

// ---------------- k_final: deterministic reduction + output ----------------
__global__ void k_final(float* out, int out_size, int nb) {
    __shared__ float sp[256], sn[256], sc[256];
    int t = threadIdx.x;
    float pt = 0.f, nt = 0.f, ct = 0.f;
    for (int b = t; b < nb; b += 256) {
        pt += g_part[b * 3 + 0];
        nt += g_part[b * 3 + 1];
        ct += g_part[b * 3 + 2];
    }
    sp[t] = pt; sn[t] = nt; sc[t] = ct;
    __syncthreads();
    for (int o = 128; o > 0; o >>= 1) {
        if (t < o) { sp[t] += sp[t + o]; sn[t] += sn[t + o]; sc[t] += sc[t + o]; }
        __syncthreads();
    }
    if (t == 0) {
        float cnt = fmaxf(sc[0], 1.f);
        float pm = sp[0] / cnt, nm = sn[0] / cnt;
        out[0] = pm + nm;
        if (out_size > 1) out[1] = pm;
        if (out_size > 2) out[2] = nm;
        for (int z = 3; z < out_size; z++) out[z] = 0.f;
    }
}

// ---------------- launch ----------------
extern "C" void kernel_launch(void* const* d_in, const int* in_sizes, int n_in,
                              void* d_out, int out_size) {
    const float* batch = (const float*)d_in[0];
    const void*  lab   = d_in[1];
    int N = in_sizes[1];
    if (N > NMAX) N = NMAX;

    static bool attr_done = false;
    if (!attr_done) {
        cudaFuncSetAttribute(k_gemm, cudaFuncAttributeMaxDynamicSharedMemorySize,
                             2 * 128 * SPAD * (int)sizeof(float));
        attr_done = true;
    }

    k_detect<<<1, 256>>>((const int*)lab, N);
    k_prep<<<(N + 255) / 256, 256>>>(lab, N);
    k_norm<<<(N + 7) / 8, 256>>>(batch, N);
    int nb = N / 128;
    int ntiles = nb * (nb + 1) / 2;
    k_gemm<<<ntiles, 256, 2 * 128 * SPAD * (int)sizeof(float)>>>(N);
    k_sums<<<(N + 7) / 8, 256>>>(N);
    k_final<<<1, 256>>>((float*)d_out, out_size, (N + 7) / 8);
}

// round 5
// speedup vs baseline: 1.4626x; 1.1789x over previous
#include <cuda_runtime.h>
#include <cuda_bf16.h>
#include <cstdint>
#include <cstddef>
#include <math.h>

#define NMAX 4096
#define DDIM 128
#define POS_W 2.0f
#define NEG_W 40.0f
#define MARGIN 0.1f
#define THRESH 0.5f

// ---------------- scratch (no allocations allowed) ----------------
__device__ float    g_xn[NMAX * DDIM];
__device__ int      g_lab[NMAX];
__device__ float    g_S[(size_t)NMAX * NMAX];
__device__ unsigned g_minpos[NMAX];
__device__ unsigned g_maxneg[NMAX];
__device__ float    g_part[3 * (NMAX / 8)];
__device__ int      g_lflag;

__device__ __forceinline__ unsigned fenc(float f) {
    unsigned u = __float_as_uint(f);
    return (u & 0x80000000u) ? ~u : (u | 0x80000000u);
}
__device__ __forceinline__ float fdec(unsigned e) {
    unsigned u = (e & 0x80000000u) ? (e ^ 0x80000000u) : ~e;
    return __uint_as_float(u);
}

__device__ __forceinline__ uint32_t smem_u32(const void* p) {
    uint32_t a;
    asm("{ .reg .u64 t; cvta.to.shared.u64 t, %1; cvt.u32.u64 %0, t; }" : "=r"(a) : "l"(p));
    return a;
}

// ldmatrix (portable, sm_75+)
#define LDSM_X4(r, ad) \
    asm volatile("ldmatrix.sync.aligned.m8n8.x4.shared.b16 {%0,%1,%2,%3}, [%4];" \
        : "=r"((r)[0]), "=r"((r)[1]), "=r"((r)[2]), "=r"((r)[3]) : "r"(ad))
#define LDSM_X2(r, ad) \
    asm volatile("ldmatrix.sync.aligned.m8n8.x2.shared.b16 {%0,%1}, [%2];" \
        : "=r"((r)[0]), "=r"((r)[1]) : "r"(ad))

// warp-level bf16 mma (portable, sm_80+)
#define MMA16816(c, a, b) \
    asm volatile("mma.sync.aligned.m16n8k16.row.col.f32.bf16.bf16.f32 " \
        "{%0,%1,%2,%3}, {%4,%5,%6,%7}, {%8,%9}, {%0,%1,%2,%3};" \
        : "+f"((c)[0]), "+f"((c)[1]), "+f"((c)[2]), "+f"((c)[3]) \
        : "r"((a)[0]), "r"((a)[1]), "r"((a)[2]), "r"((a)[3]), "r"((b)[0]), "r"((b)[1]))

// smem layout (bytes). bf16 tiles [128][136] (272B row stride -> ldmatrix conflict-free)
#define TLD       136
#define TILE_B    (128 * TLD * 2)
#define OFF_LBLR  0
#define OFF_LBLC  512
#define OFF_AHI   1024
#define OFF_ALO   (OFF_AHI + TILE_B)
#define OFF_BHI   (OFF_ALO + TILE_B)
#define OFF_BLO   (OFF_BHI + TILE_B)
#define OFF_STAGE (OFF_BLO + TILE_B)
#define SLD       66
#define SMEM_TOTAL (OFF_STAGE + 128 * SLD * 4)

__device__ __forceinline__ void split2(float x, float y, uint32_t& hi, uint32_t& lo) {
    __nv_bfloat16 hx = __float2bfloat16(x), hy = __float2bfloat16(y);
    __nv_bfloat16 lx = __float2bfloat16(x - __bfloat162float(hx));
    __nv_bfloat16 ly = __float2bfloat16(y - __bfloat162float(hy));
    unsigned short a = *(unsigned short*)&hx, b = *(unsigned short*)&hy;
    unsigned short c = *(unsigned short*)&lx, d = *(unsigned short*)&ly;
    hi = (uint32_t)a | ((uint32_t)b << 16);
    lo = (uint32_t)c | ((uint32_t)d << 16);
}

// ---------------- small kernels ----------------
__global__ void k_detect(const int* __restrict__ lab32, int N) {
    __shared__ int s;
    if (threadIdx.x == 0) s = 0;
    __syncthreads();
    int any = 0;
    for (int i = 1 + 2 * (int)threadIdx.x; i < N; i += 2 * (int)blockDim.x)
        if (lab32[i] != 0) any = 1;
    if (any) atomicOr(&s, 1);
    __syncthreads();
    if (threadIdx.x == 0) g_lflag = s;
}

__global__ void k_prep(const void* __restrict__ labv, int N) {
    int i = blockIdx.x * blockDim.x + threadIdx.x;
    if (i >= N) return;
    int v;
    if (g_lflag) v = ((const int*)labv)[i];
    else         v = (int)(((const long long*)labv)[i]);
    g_lab[i]    = v;
    g_minpos[i] = fenc(1e9f);
    g_maxneg[i] = fenc(-1e9f);
}

__global__ void k_norm(const float* __restrict__ x, int N) {
    int warp = threadIdx.x >> 5, lane = threadIdx.x & 31;
    int row = blockIdx.x * 8 + warp;
    if (row >= N) return;
    float4 v = *(const float4*)(x + (size_t)row * DDIM + lane * 4);
    float ss = v.x * v.x + v.y * v.y + v.z * v.z + v.w * v.w;
#pragma unroll
    for (int o = 16; o > 0; o >>= 1) ss += __shfl_xor_sync(0xffffffffu, ss, o);
    float inv = 1.0f / sqrtf(ss);
    *(float4*)(g_xn + (size_t)row * DDIM + lane * 4) =
        make_float4(v.x * inv, v.y * inv, v.z * inv, v.w * inv);
}

// ---------------- HMMA tile kernel (split-bf16, 3 products) ----------------
__global__ __launch_bounds__(256, 1) void k_gemm_mma(int N) {
    extern __shared__ char smem[];
    uint32_t sb = smem_u32(smem);
    float* stage = (float*)(smem + OFF_STAGE);
    int* lblRow = (int*)(smem + OFF_LBLR);
    int* lblCol = (int*)(smem + OFF_LBLC);

    int tid = threadIdx.x, wid = tid >> 5, lane = tid & 31;

    // upper-triangular tile mapping (by <= bx)
    int t = blockIdx.x;
    int bx = (int)((sqrtf(8.0f * (float)t + 1.0f) - 1.0f) * 0.5f);
    while ((bx + 1) * (bx + 2) / 2 <= t) bx++;
    while (bx * (bx + 1) / 2 > t) bx--;
    int by = t - bx * (bx + 1) / 2;
    int row0 = by * 128, col0 = bx * 128;
    bool diag = (bx == by);

    if (tid < 128) lblRow[tid] = g_lab[row0 + tid];
    else           lblCol[tid - 128] = g_lab[col0 + tid - 128];

    // load + split A rows (row0..) and B rows (col0..) into 4 bf16 tiles
    {
        int r = tid >> 1, ch = (tid & 1) * 64;
#pragma unroll
        for (int q = 0; q < 16; q++) {
            int col = ch + q * 4;
            uint32_t off = (uint32_t)(r * TLD + col) * 2u;
            float4 va = *(const float4*)(g_xn + (size_t)(row0 + r) * DDIM + col);
            uint32_t h0, l0, h1, l1;
            split2(va.x, va.y, h0, l0);
            split2(va.z, va.w, h1, l1);
            *(uint2*)(smem + OFF_AHI + off) = make_uint2(h0, h1);
            *(uint2*)(smem + OFF_ALO + off) = make_uint2(l0, l1);
            float4 vb = *(const float4*)(g_xn + (size_t)(col0 + r) * DDIM + col);
            split2(vb.x, vb.y, h0, l0);
            split2(vb.z, vb.w, h1, l1);
            *(uint2*)(smem + OFF_BHI + off) = make_uint2(h0, h1);
            *(uint2*)(smem + OFF_BLO + off) = make_uint2(l0, l1);
        }
    }
    __syncthreads();

    // warp tiling: 8 warps -> 2 (m) x 4 (n); warp tile 64x32
    int warp_m = wid >> 2, warp_n = wid & 3;
    int m0 = warp_m * 64, n0 = warp_n * 32;

    float acc[4][4][4];
#pragma unroll
    for (int i = 0; i < 4; i++)
#pragma unroll
        for (int j = 0; j < 4; j++)
#pragma unroll
            for (int r = 0; r < 4; r++) acc[i][j][r] = 0.f;

    // per-lane ldmatrix address bases
    int aRow = (lane & 7) + ((lane >> 3) & 1) * 8;     // row within 16
    int aColH = ((lane >> 4) & 1) * 8;                 // col half
    int l16 = lane & 15;
    int bRow = l16 & 7;
    int bColH = ((l16 >> 3) & 1) * 8;

    uint32_t aOffLane = (uint32_t)((m0 + aRow) * TLD + aColH) * 2u;
    uint32_t bOffLane = (uint32_t)((n0 + bRow) * TLD + bColH) * 2u;

    uint32_t aBase[3] = { sb + OFF_AHI + aOffLane, sb + OFF_AHI + aOffLane, sb + OFF_ALO + aOffLane };
    uint32_t bBase[3] = { sb + OFF_BHI + bOffLane, sb + OFF_BLO + bOffLane, sb + OFF_BHI + bOffLane };

#pragma unroll
    for (int p = 0; p < 3; p++) {
        uint32_t aB = aBase[p], bB = bBase[p];
#pragma unroll
        for (int k0 = 0; k0 < 128; k0 += 16) {
            uint32_t af[4][4], bf[4][2];
#pragma unroll
            for (int i = 0; i < 4; i++)
                LDSM_X4(af[i], aB + (uint32_t)(i * 16 * TLD + k0) * 2u);
#pragma unroll
            for (int j = 0; j < 4; j++)
                LDSM_X2(bf[j], bB + (uint32_t)(j * 8 * TLD + k0) * 2u);
#pragma unroll
            for (int i = 0; i < 4; i++)
#pragma unroll
                for (int j = 0; j < 4; j++)
                    MMA16816(acc[i][j], af[i], bf[j]);
        }
    }

    // ---- epilogue: stage 64-col chunks, store S + S^T, fused stats ----
    int q = lane >> 2, tq = lane & 3;
    float rmn = 1e9f, rmx = -1e9f;
    int li = (tid < 128) ? lblRow[tid] : 0;

#pragma unroll
    for (int chunk = 0; chunk < 2; chunk++) {
        __syncthreads();
        if ((warp_n >> 1) == chunk) {
            int nloc = (warp_n & 1) * 32;
#pragma unroll
            for (int i = 0; i < 4; i++) {
#pragma unroll
                for (int j = 0; j < 4; j++) {
                    int r = m0 + 16 * i + q;
                    int c = nloc + 8 * j + 2 * tq;
                    stage[r * SLD + c]           = acc[i][j][0];
                    stage[r * SLD + c + 1]       = acc[i][j][1];
                    stage[(r + 8) * SLD + c]     = acc[i][j][2];
                    stage[(r + 8) * SLD + c + 1] = acc[i][j][3];
                }
            }
        }
        __syncthreads();

        // coalesced row-major store of this 128x64 chunk
        {
            int quad = tid & 15, rb = tid >> 4;
#pragma unroll
            for (int it = 0; it < 8; it++) {
                int r = rb + 16 * it;
                const float* sp = &stage[r * SLD + 4 * quad];
                float4 v = make_float4(sp[0], sp[1], sp[2], sp[3]);
                *(float4*)(g_S + (size_t)(row0 + r) * N + col0 + chunk * 64 + 4 * quad) = v;
            }
        }

        // row stats: thread tid<128 scans its row's 64 cols
        if (tid < 128) {
            int selfc = (row0 + tid) - (col0 + chunk * 64);
#pragma unroll 8
            for (int c = 0; c < 64; c++) {
                float s = stage[tid * SLD + c];
                int lj = lblCol[chunk * 64 + c];
                if (li == lj) {
                    if (c != selfc && s < rmn) rmn = s;
                } else if (s > rmx) rmx = s;
            }
        }

        // transposed store + column stats (off-diagonal tiles)
        if (!diag) {
#pragma unroll
            for (int cit = 0; cit < 8; cit++) {
                int c = wid + 8 * cit;
                int colT = col0 + chunk * 64 + c;
                int ljc = lblCol[chunk * 64 + c];
                float cm = 1e9f, cM = -1e9f;
#pragma unroll
                for (int m = 0; m < 4; m++) {
                    int r = lane + 32 * m;
                    float s = stage[r * SLD + c];
                    int lr = lblRow[r];
                    if (lr == ljc) { if (s < cm) cm = s; }
                    else if (s > cM) cM = s;
                    g_S[(size_t)colT * N + row0 + r] = s;
                }
#pragma unroll
                for (int o = 16; o > 0; o >>= 1) {
                    cm = fminf(cm, __shfl_xor_sync(0xffffffffu, cm, o));
                    cM = fmaxf(cM, __shfl_xor_sync(0xffffffffu, cM, o));
                }
                if (lane == 0) {
                    atomicMin(&g_minpos[colT], fenc(cm));
                    atomicMax(&g_maxneg[colT], fenc(cM));
                }
            }
        }
    }

    if (tid < 128) {
        atomicMin(&g_minpos[row0 + tid], fenc(rmn));
        atomicMax(&g_maxneg[row0 + tid], fenc(rmx));
    }
}

// ---------------- k_sums ----------------
__global__ __launch_bounds__(256) void k_sums(int N) {
    __shared__ int slbl[NMAX];
    __shared__ float spt[8], snt[8], sct[8];
    for (int j = threadIdx.x; j < N; j += 256) slbl[j] = g_lab[j];
    __syncthreads();

    int warp = threadIdx.x >> 5, lane = threadIdx.x & 31;
    int i = blockIdx.x * 8 + warp;

    float minp = fdec(g_minpos[i]);
    float maxn = fdec(g_maxneg[i]);
    int li = slbl[i];
    float psum = 0.f, nsum = 0.f;
    int psel = 0, nsel = 0;
    const float* Srow = g_S + (size_t)i * N;

    for (int j0 = lane * 4; j0 < N; j0 += 128) {
        float4 s4 = *(const float4*)(Srow + j0);
        float sv[4] = {s4.x, s4.y, s4.z, s4.w};
#pragma unroll
        for (int qq = 0; qq < 4; qq++) {
            int j = j0 + qq;
            float s = sv[qq];
            if (slbl[j] == li) {
                if (j != i && (s - MARGIN < maxn)) {
                    psel = 1; psum += __expf(-POS_W * (s - THRESH));
                }
            } else {
                if (s + MARGIN > minp) {
                    nsel = 1; nsum += __expf(NEG_W * (s - THRESH));
                }
            }
        }
    }
#pragma unroll
    for (int o = 16; o > 0; o >>= 1) {
        psum += __shfl_xor_sync(0xffffffffu, psum, o);
        nsum += __shfl_xor_sync(0xffffffffu, nsum, o);
    }
    psel = (__ballot_sync(0xffffffffu, psel) != 0);
    nsel = (__ballot_sync(0xffffffffu, nsel) != 0);

    if (lane == 0) {
        bool valid = (minp < 5e8f) && (maxn > -5e8f) && psel && nsel;
        spt[warp] = valid ? (log1pf(psum) * (1.0f / POS_W)) : 0.f;
        snt[warp] = valid ? (log1pf(nsum) * (1.0f / NEG_W)) : 0.f;
        sct[warp] = valid ? 1.f : 0.f;
    }
    __syncthreads();
    if (threadIdx.x == 0) {
        float pt = 0.f, nt = 0.f, ct = 0.f;
        for (int w = 0; w < 8; w++) { pt += spt[w]; nt += snt[w]; ct += sct[w]; }
        g_part[blockIdx.x * 3 + 0] = pt;
        g_part[blockIdx.x * 3 + 1] = nt;
        g_part[blockIdx.x * 3 + 2] = ct;
    }
}

__global__ void k_final(float* out, int out_size, int nb) {
    __shared__ float sp[256], sn[256], sc[256];
    int t = threadIdx.x;
    float pt = 0.f, nt = 0.f, ct = 0.f;
    for (int b = t; b < nb; b += 256) {
        pt += g_part[b * 3 + 0];
        nt += g_part[b * 3 + 1];
        ct += g_part[b * 3 + 2];
    }
    sp[t] = pt; sn[t] = nt; sc[t] = ct;
    __syncthreads();
    for (int o = 128; o > 0; o >>= 1) {
        if (t < o) { sp[t] += sp[t + o]; sn[t] += sn[t + o]; sc[t] += sc[t + o]; }
        __syncthreads();
    }
    if (t == 0) {
        float cnt = fmaxf(sc[0], 1.f);
        float pm = sp[0] / cnt, nm = sn[0] / cnt;
        out[0] = pm + nm;
        if (out_size > 1) out[1] = pm;
        if (out_size > 2) out[2] = nm;
        for (int z = 3; z < out_size; z++) out[z] = 0.f;
    }
}

// ---------------- launch ----------------
extern "C" void kernel_launch(void* const* d_in, const int* in_sizes, int n_in,
                              void* d_out, int out_size) {
    const float* batch = (const float*)d_in[0];
    const void*  lab   = d_in[1];
    int N = in_sizes[1];
    if (N > NMAX) N = NMAX;

    static bool attr_done = false;
    if (!attr_done) {
        cudaFuncSetAttribute(k_gemm_mma, cudaFuncAttributeMaxDynamicSharedMemorySize,
                             SMEM_TOTAL);
        attr_done = true;
    }

    k_detect<<<1, 256>>>((const int*)lab, N);
    k_prep<<<(N + 255) / 256, 256>>>(lab, N);
    k_norm<<<(N + 7) / 8, 256>>>(batch, N);
    int nb = N / 128;
    int ntiles = nb * (nb + 1) / 2;
    k_gemm_mma<<<ntiles, 256, SMEM_TOTAL>>>(N);
    k_sums<<<(N + 7) / 8, 256>>>(N);
    k_final<<<1, 256>>>((float*)d_out, out_size, (N + 7) / 8);
}